// round 14
// baseline (speedup 1.0000x reference)
#include <cuda_runtime.h>
#include <cuda_fp16.h>
#include <cuda_bf16.h>

#define N_NODES 100000
#define N_EDGES 1600000
#define F_IN 128
#define N_H 3
#define N_D 16
#define HD 48
#define NEG_SLOPE 0.2f

#define SCAN_B 256
#define NB ((N_NODES + SCAN_B - 1) / SCAN_B)   // 391

#define GB_NODES 128          // nodes per gemm block
#define GB_THREADS 256

// Scratch (device globals)
__device__ float  g_feat[N_NODES * HD];     // projected features (N,48) fp32
__device__ __half g_feat_h[N_NODES * HD];   // fp16 shadow for agg gathers
__device__ float4 g_el[N_NODES];            // (el0,el1,el2,_)
__device__ float4 g_er[N_NODES];            // (er0,er1,er2,_)
__device__ int    g_esrc[N_EDGES];          // src index per edge, grouped by dst
__device__ unsigned short g_pos[N_EDGES];   // edge rank within its dst segment
__device__ int    g_count[N_NODES];         // in-degree
__device__ int    g_off[N_NODES];           // CSR segment start
__device__ int    g_bsum[NB];               // per-block count sums
__device__ int    g_bbase[NB];              // exclusive scan of block sums

// ---------------------------------------------------------------------------
// Kernel 0: zero degree counters
// ---------------------------------------------------------------------------
__global__ void k_init() {
    int i = blockIdx.x * blockDim.x + threadIdx.x;
    if (i < N_NODES) g_count[i] = 0;
}

// ---------------------------------------------------------------------------
// Kernel 1: register-tiled GEMM, vectorized SMEM reads.
// Thread tile 4 nodes x 6 cols; per k-step 1 LDS.128 + 3 LDS.64 feed 24 FFMA.
// Epilogue also writes the fp16 shadow (cg6 is even -> half2-aligned).
// ---------------------------------------------------------------------------
__global__ __launch_bounds__(GB_THREADS) void k_gemm(const float* __restrict__ x,
                                                     const float* __restrict__ W)
{
    __shared__ __align__(16) float Wt[F_IN][HD];      // Wt[k][j] = W[j*F_IN+k]
    __shared__ __align__(16) float Xs[16][GB_NODES];  // one k-chunk of x

    int tid = threadIdx.x;
    for (int i = tid; i < HD * F_IN; i += GB_THREADS) {
        int j = i / F_IN, k = i % F_IN;
        Wt[k][j] = W[i];
    }

    int node_base = blockIdx.x * GB_NODES;
    int ng = tid >> 3;            // node group 0..31 (4 nodes each)
    int cg = tid & 7;             // col group 0..7 (6 cols each)
    int ng4 = ng * 4;
    int cg6 = cg * 6;

    int ln = tid & 127;
    int lk = (tid >> 7) * 8;
    int gnode = node_base + ln;
    bool ldok = (gnode < N_NODES);
    const float* xrow = x + (size_t)gnode * F_IN + lk;

    float acc[4][6];
#pragma unroll
    for (int i = 0; i < 4; i++)
#pragma unroll
        for (int c = 0; c < 6; c++) acc[i][c] = 0.f;

    for (int kk = 0; kk < F_IN; kk += 16) {
        __syncthreads();
        float4 v0 = ldok ? *(const float4*)(xrow + kk)     : make_float4(0.f,0.f,0.f,0.f);
        float4 v1 = ldok ? *(const float4*)(xrow + kk + 4) : make_float4(0.f,0.f,0.f,0.f);
        Xs[lk + 0][ln] = v0.x; Xs[lk + 1][ln] = v0.y;
        Xs[lk + 2][ln] = v0.z; Xs[lk + 3][ln] = v0.w;
        Xs[lk + 4][ln] = v1.x; Xs[lk + 5][ln] = v1.y;
        Xs[lk + 6][ln] = v1.z; Xs[lk + 7][ln] = v1.w;
        __syncthreads();

#pragma unroll
        for (int k = 0; k < 16; k++) {
            float4 a = *(const float4*)&Xs[k][ng4];            // LDS.128, bcast
            const float2* wr = (const float2*)&Wt[kk + k][cg6];
            float2 w01 = wr[0];
            float2 w23 = wr[1];
            float2 w45 = wr[2];
            acc[0][0] = fmaf(a.x, w01.x, acc[0][0]); acc[0][1] = fmaf(a.x, w01.y, acc[0][1]);
            acc[0][2] = fmaf(a.x, w23.x, acc[0][2]); acc[0][3] = fmaf(a.x, w23.y, acc[0][3]);
            acc[0][4] = fmaf(a.x, w45.x, acc[0][4]); acc[0][5] = fmaf(a.x, w45.y, acc[0][5]);
            acc[1][0] = fmaf(a.y, w01.x, acc[1][0]); acc[1][1] = fmaf(a.y, w01.y, acc[1][1]);
            acc[1][2] = fmaf(a.y, w23.x, acc[1][2]); acc[1][3] = fmaf(a.y, w23.y, acc[1][3]);
            acc[1][4] = fmaf(a.y, w45.x, acc[1][4]); acc[1][5] = fmaf(a.y, w45.y, acc[1][5]);
            acc[2][0] = fmaf(a.z, w01.x, acc[2][0]); acc[2][1] = fmaf(a.z, w01.y, acc[2][1]);
            acc[2][2] = fmaf(a.z, w23.x, acc[2][2]); acc[2][3] = fmaf(a.z, w23.y, acc[2][3]);
            acc[2][4] = fmaf(a.z, w45.x, acc[2][4]); acc[2][5] = fmaf(a.z, w45.y, acc[2][5]);
            acc[3][0] = fmaf(a.w, w01.x, acc[3][0]); acc[3][1] = fmaf(a.w, w01.y, acc[3][1]);
            acc[3][2] = fmaf(a.w, w23.x, acc[3][2]); acc[3][3] = fmaf(a.w, w23.y, acc[3][3]);
            acc[3][4] = fmaf(a.w, w45.x, acc[3][4]); acc[3][5] = fmaf(a.w, w45.y, acc[3][5]);
        }
    }

#pragma unroll
    for (int i = 0; i < 4; i++) {
        int n = node_base + ng4 + i;
        if (n < N_NODES) {
            float* dstp = g_feat + (size_t)n * HD + cg6;
            *(float2*)(dstp + 0) = make_float2(acc[i][0], acc[i][1]);
            *(float2*)(dstp + 2) = make_float2(acc[i][2], acc[i][3]);
            *(float2*)(dstp + 4) = make_float2(acc[i][4], acc[i][5]);
            __half2* hp = (__half2*)(g_feat_h + (size_t)n * HD + cg6);
            hp[0] = __floats2half2_rn(acc[i][0], acc[i][1]);
            hp[1] = __floats2half2_rn(acc[i][2], acc[i][3]);
            hp[2] = __floats2half2_rn(acc[i][4], acc[i][5]);
        }
    }
}

// ---------------------------------------------------------------------------
// Kernel 1b: attention logits el/er per node (reads freshly-written g_feat).
// ---------------------------------------------------------------------------
__global__ __launch_bounds__(256) void k_logits(const float* __restrict__ al,
                                                const float* __restrict__ ar)
{
    __shared__ float als[HD], ars[HD];
    if (threadIdx.x < HD) {
        als[threadIdx.x] = al[threadIdx.x];
        ars[threadIdx.x] = ar[threadIdx.x];
    }
    __syncthreads();

    int n = blockIdx.x * 256 + threadIdx.x;
    if (n >= N_NODES) return;

    const float4* f4 = (const float4*)(g_feat + (size_t)n * HD);
    float el[N_H] = {0.f, 0.f, 0.f};
    float er[N_H] = {0.f, 0.f, 0.f};
#pragma unroll
    for (int q = 0; q < HD / 4; q++) {
        float4 f = f4[q];
        int j = 4 * q;
        int h = j >> 4;
        el[h] = fmaf(f.x, als[j], fmaf(f.y, als[j+1], fmaf(f.z, als[j+2], fmaf(f.w, als[j+3], el[h]))));
        er[h] = fmaf(f.x, ars[j], fmaf(f.y, ars[j+1], fmaf(f.z, ars[j+2], fmaf(f.w, ars[j+3], er[h]))));
    }
    g_el[n] = make_float4(el[0], el[1], el[2], 0.f);
    g_er[n] = make_float4(er[0], er[1], er[2], 0.f);
}

// ---------------------------------------------------------------------------
// Kernel 2: in-degree histogram; atomic return value = edge rank in segment.
// ---------------------------------------------------------------------------
__global__ void k_hist(const int* __restrict__ dst) {
    int e = blockIdx.x * blockDim.x + threadIdx.x;
    if (e >= N_EDGES) return;
    int p = atomicAdd(&g_count[dst[e]], 1);
    g_pos[e] = (unsigned short)p;
}

// ---------------------------------------------------------------------------
// Kernel 3a/3b/3c: hierarchical exclusive scan of g_count -> g_off
// ---------------------------------------------------------------------------
__global__ __launch_bounds__(SCAN_B) void k_bsum() {
    __shared__ int sh[SCAN_B];
    int i = blockIdx.x * SCAN_B + threadIdx.x;
    sh[threadIdx.x] = (i < N_NODES) ? g_count[i] : 0;
    __syncthreads();
    for (int off = SCAN_B / 2; off > 0; off >>= 1) {
        if (threadIdx.x < off) sh[threadIdx.x] += sh[threadIdx.x + off];
        __syncthreads();
    }
    if (threadIdx.x == 0) g_bsum[blockIdx.x] = sh[0];
}

__global__ __launch_bounds__(512) void k_sscan() {
    __shared__ int sh[512];
    int t = threadIdx.x;
    sh[t] = (t < NB) ? g_bsum[t] : 0;
    __syncthreads();
    for (int off = 1; off < 512; off <<= 1) {
        int v = (t >= off) ? sh[t - off] : 0;
        __syncthreads();
        sh[t] += v;
        __syncthreads();
    }
    if (t < NB) g_bbase[t] = (t == 0) ? 0 : sh[t - 1];
}

__global__ __launch_bounds__(SCAN_B) void k_off() {
    __shared__ int sh[SCAN_B];
    int i = blockIdx.x * SCAN_B + threadIdx.x;
    int t = threadIdx.x;
    int c = (i < N_NODES) ? g_count[i] : 0;
    sh[t] = c;
    __syncthreads();
    for (int off = 1; off < SCAN_B; off <<= 1) {
        int v = (t >= off) ? sh[t - off] : 0;
        __syncthreads();
        sh[t] += v;
        __syncthreads();
    }
    if (i < N_NODES) {
        g_off[i] = g_bbase[blockIdx.x] + sh[t] - c;
    }
}

// ---------------------------------------------------------------------------
// Kernel 4: edge scatter — atomic-free, 4B payload. pos = off[d] + rank.
// ---------------------------------------------------------------------------
__global__ void k_scatter(const int* __restrict__ src, const int* __restrict__ dst) {
    int e = blockIdx.x * blockDim.x + threadIdx.x;
    if (e >= N_EDGES) return;
    int d = dst[e];
    int pos = g_off[d] + (int)g_pos[e];
    g_esrc[pos] = src[e];
}

// ---------------------------------------------------------------------------
// Kernel 5: per-dst aggregation, 12 threads/node; fp16 feat gathers
// (3 L2 sectors/edge instead of 6), fp32 accumulate, exact fp32 blend.
// Attention recomputed: a = exp(leakyrelu(el[s].h + er[d].h)).
// Max-subtraction skipped: |e| <= ~4, softmax shift-invariant (fp32-safe).
// ---------------------------------------------------------------------------
__global__ __launch_bounds__(192) void k_agg(const float* __restrict__ lin,
                                             float* __restrict__ out) {
    int d = blockIdx.x * 16 + threadIdx.y;
    if (d >= N_NODES) return;
    int tx = threadIdx.x;       // 0..11
    int c4 = tx * 4;            // col base 0,4,...,44
    int h = tx >> 2;            // head 0..2

    int beg = g_off[d];
    int cnt = g_count[d];
    int end = beg + cnt;

    float4 R4 = g_er[d];
    float er_h = (h == 0) ? R4.x : ((h == 1) ? R4.y : R4.z);

    float4 num0 = make_float4(0.f, 0.f, 0.f, 0.f);
    float4 num1 = make_float4(0.f, 0.f, 0.f, 0.f);
    float den0 = 0.f, den1 = 0.f;

    int p = beg;
    for (; p + 2 <= end; p += 2) {
        int s0 = g_esrc[p];
        int s1 = g_esrc[p + 1];
        float4 L0 = g_el[s0];
        float4 L1 = g_el[s1];
        const __half2* hp0 = (const __half2*)(g_feat_h + (size_t)s0 * HD + c4);
        const __half2* hp1 = (const __half2*)(g_feat_h + (size_t)s1 * HD + c4);
        __half2 h0a = hp0[0], h0b = hp0[1];
        __half2 h1a = hp1[0], h1b = hp1[1];
        float2 f0a = __half22float2(h0a), f0b = __half22float2(h0b);
        float2 f1a = __half22float2(h1a), f1b = __half22float2(h1b);
        float v0 = ((h == 0) ? L0.x : ((h == 1) ? L0.y : L0.z)) + er_h;
        float v1 = ((h == 0) ? L1.x : ((h == 1) ? L1.y : L1.z)) + er_h;
        v0 = v0 > 0.f ? v0 : NEG_SLOPE * v0;
        v1 = v1 > 0.f ? v1 : NEG_SLOPE * v1;
        float a0 = __expf(v0);
        float a1 = __expf(v1);
        num0.x = fmaf(a0, f0a.x, num0.x); num0.y = fmaf(a0, f0a.y, num0.y);
        num0.z = fmaf(a0, f0b.x, num0.z); num0.w = fmaf(a0, f0b.y, num0.w);
        den0 += a0;
        num1.x = fmaf(a1, f1a.x, num1.x); num1.y = fmaf(a1, f1a.y, num1.y);
        num1.z = fmaf(a1, f1b.x, num1.z); num1.w = fmaf(a1, f1b.y, num1.w);
        den1 += a1;
    }
    if (p < end) {
        int s = g_esrc[p];
        float4 L = g_el[s];
        const __half2* hp = (const __half2*)(g_feat_h + (size_t)s * HD + c4);
        __half2 ha = hp[0], hb = hp[1];
        float2 fa = __half22float2(ha), fb = __half22float2(hb);
        float v = ((h == 0) ? L.x : ((h == 1) ? L.y : L.z)) + er_h;
        v = v > 0.f ? v : NEG_SLOPE * v;
        float a = __expf(v);
        num0.x = fmaf(a, fa.x, num0.x); num0.y = fmaf(a, fa.y, num0.y);
        num0.z = fmaf(a, fb.x, num0.z); num0.w = fmaf(a, fb.y, num0.w);
        den0 += a;
    }

    float den = den0 + den1;
    float inv = (cnt > 0) ? (1.f / den) : 0.f;
    float l = lin[d];
    float4 fd = *(const float4*)(g_feat + (size_t)d * HD + c4);
    float4 r;
    r.x = (1.f - l) * ((num0.x + num1.x) * inv) + l * fd.x;
    r.y = (1.f - l) * ((num0.y + num1.y) * inv) + l * fd.y;
    r.z = (1.f - l) * ((num0.z + num1.z) * inv) + l * fd.z;
    r.w = (1.f - l) * ((num0.w + num1.w) * inv) + l * fd.w;
    *(float4*)(out + (size_t)d * HD + c4) = r;
}

// ---------------------------------------------------------------------------
extern "C" void kernel_launch(void* const* d_in, const int* in_sizes, int n_in,
                              void* d_out, int out_size) {
    const float* x   = (const float*)d_in[0];
    const float* W   = (const float*)d_in[1];
    const float* al  = (const float*)d_in[2];
    const float* ar  = (const float*)d_in[3];
    const float* lin = (const float*)d_in[4];
    const int*   src = (const int*)d_in[5];
    const int*   dst = (const int*)d_in[6];
    float* out = (float*)d_out;

    k_init<<<(N_NODES + 255) / 256, 256>>>();
    k_gemm<<<(N_NODES + GB_NODES - 1) / GB_NODES, GB_THREADS>>>(x, W);
    k_logits<<<(N_NODES + 255) / 256, 256>>>(al, ar);
    k_hist<<<(N_EDGES + 255) / 256, 256>>>(dst);
    k_bsum<<<NB, SCAN_B>>>();
    k_sscan<<<1, 512>>>();
    k_off<<<NB, SCAN_B>>>();
    k_scatter<<<(N_EDGES + 255) / 256, 256>>>(src, dst);
    dim3 aggBlock(12, 16);
    k_agg<<<(N_NODES + 15) / 16, aggBlock>>>(lin, out);
}

// round 15
// speedup vs baseline: 1.0265x; 1.0265x over previous
#include <cuda_runtime.h>
#include <cuda_bf16.h>

#define N_NODES 100000
#define N_EDGES 1600000
#define F_IN 128
#define N_H 3
#define N_D 16
#define HD 48
#define NEG_SLOPE 0.2f

#define SCAN_B 256
#define NB ((N_NODES + SCAN_B - 1) / SCAN_B)   // 391

#define GB_NODES 128          // nodes per gemm block
#define GB_THREADS 256

// Scratch (device globals)
__device__ float  g_feat[N_NODES * HD];     // projected features (N,48)
__device__ float4 g_el[N_NODES];            // (el0,el1,el2,_)
__device__ float4 g_er[N_NODES];            // (er0,er1,er2,_)
__device__ int    g_esrc[N_EDGES];          // src index per edge, grouped by dst
__device__ unsigned short g_pos[N_EDGES];   // edge rank within its dst segment
__device__ int    g_count[N_NODES];         // in-degree
__device__ int    g_off[N_NODES];           // CSR segment start
__device__ int    g_bsum[NB];               // per-block count sums
__device__ int    g_bbase[NB];              // exclusive scan of block sums

// ---------------------------------------------------------------------------
// Kernel 0: zero degree counters
// ---------------------------------------------------------------------------
__global__ void k_init() {
    int i = blockIdx.x * blockDim.x + threadIdx.x;
    if (i < N_NODES) g_count[i] = 0;
}

// ---------------------------------------------------------------------------
// Kernel 1: register-tiled GEMM with FUSED logits epilogue.
// Thread tile 4 nodes x 6 cols; per k-step 1 LDS.128 + 3 LDS.64 feed 24 FFMA.
// Epilogue: per-head partial dots (al/ar) accumulated via smem atomics into
// a 128-node x 3-head table -> g_el/g_er, killing the separate logits pass.
// ---------------------------------------------------------------------------
__global__ __launch_bounds__(GB_THREADS) void k_gemm(const float* __restrict__ x,
                                                     const float* __restrict__ W,
                                                     const float* __restrict__ al,
                                                     const float* __restrict__ ar)
{
    __shared__ __align__(16) float Wt[F_IN][HD];      // Wt[k][j] = W[j*F_IN+k]
    __shared__ __align__(16) float Xs[16][GB_NODES];  // one k-chunk of x
    __shared__ float ELs[GB_NODES][4];                // per-head el partials
    __shared__ float ERs[GB_NODES][4];                // per-head er partials
    __shared__ float als[HD], ars[HD];

    int tid = threadIdx.x;
    for (int i = tid; i < HD * F_IN; i += GB_THREADS) {
        int j = i / F_IN, k = i % F_IN;
        Wt[k][j] = W[i];
    }
    if (tid < HD) {
        als[tid] = al[tid];
        ars[tid] = ar[tid];
    }
    for (int i = tid; i < GB_NODES * 4; i += GB_THREADS) {
        ELs[i >> 2][i & 3] = 0.f;
        ERs[i >> 2][i & 3] = 0.f;
    }

    int node_base = blockIdx.x * GB_NODES;
    int ng = tid >> 3;            // node group 0..31 (4 nodes each)
    int cg = tid & 7;             // col group 0..7 (6 cols each)
    int ng4 = ng * 4;
    int cg6 = cg * 6;

    int ln = tid & 127;
    int lk = (tid >> 7) * 8;
    int gnode = node_base + ln;
    bool ldok = (gnode < N_NODES);
    const float* xrow = x + (size_t)gnode * F_IN + lk;

    float acc[4][6];
#pragma unroll
    for (int i = 0; i < 4; i++)
#pragma unroll
        for (int c = 0; c < 6; c++) acc[i][c] = 0.f;

    for (int kk = 0; kk < F_IN; kk += 16) {
        __syncthreads();
        float4 v0 = ldok ? *(const float4*)(xrow + kk)     : make_float4(0.f,0.f,0.f,0.f);
        float4 v1 = ldok ? *(const float4*)(xrow + kk + 4) : make_float4(0.f,0.f,0.f,0.f);
        Xs[lk + 0][ln] = v0.x; Xs[lk + 1][ln] = v0.y;
        Xs[lk + 2][ln] = v0.z; Xs[lk + 3][ln] = v0.w;
        Xs[lk + 4][ln] = v1.x; Xs[lk + 5][ln] = v1.y;
        Xs[lk + 6][ln] = v1.z; Xs[lk + 7][ln] = v1.w;
        __syncthreads();

#pragma unroll
        for (int k = 0; k < 16; k++) {
            float4 a = *(const float4*)&Xs[k][ng4];            // LDS.128, bcast
            const float2* wr = (const float2*)&Wt[kk + k][cg6];
            float2 w01 = wr[0];
            float2 w23 = wr[1];
            float2 w45 = wr[2];
            acc[0][0] = fmaf(a.x, w01.x, acc[0][0]); acc[0][1] = fmaf(a.x, w01.y, acc[0][1]);
            acc[0][2] = fmaf(a.x, w23.x, acc[0][2]); acc[0][3] = fmaf(a.x, w23.y, acc[0][3]);
            acc[0][4] = fmaf(a.x, w45.x, acc[0][4]); acc[0][5] = fmaf(a.x, w45.y, acc[0][5]);
            acc[1][0] = fmaf(a.y, w01.x, acc[1][0]); acc[1][1] = fmaf(a.y, w01.y, acc[1][1]);
            acc[1][2] = fmaf(a.y, w23.x, acc[1][2]); acc[1][3] = fmaf(a.y, w23.y, acc[1][3]);
            acc[1][4] = fmaf(a.y, w45.x, acc[1][4]); acc[1][5] = fmaf(a.y, w45.y, acc[1][5]);
            acc[2][0] = fmaf(a.z, w01.x, acc[2][0]); acc[2][1] = fmaf(a.z, w01.y, acc[2][1]);
            acc[2][2] = fmaf(a.z, w23.x, acc[2][2]); acc[2][3] = fmaf(a.z, w23.y, acc[2][3]);
            acc[2][4] = fmaf(a.z, w45.x, acc[2][4]); acc[2][5] = fmaf(a.z, w45.y, acc[2][5]);
            acc[3][0] = fmaf(a.w, w01.x, acc[3][0]); acc[3][1] = fmaf(a.w, w01.y, acc[3][1]);
            acc[3][2] = fmaf(a.w, w23.x, acc[3][2]); acc[3][3] = fmaf(a.w, w23.y, acc[3][3]);
            acc[3][4] = fmaf(a.w, w45.x, acc[3][4]); acc[3][5] = fmaf(a.w, w45.y, acc[3][5]);
        }
    }

    // feat stores
#pragma unroll
    for (int i = 0; i < 4; i++) {
        int n = node_base + ng4 + i;
        if (n < N_NODES) {
            float* dstp = g_feat + (size_t)n * HD + cg6;
            *(float2*)(dstp + 0) = make_float2(acc[i][0], acc[i][1]);
            *(float2*)(dstp + 2) = make_float2(acc[i][2], acc[i][3]);
            *(float2*)(dstp + 4) = make_float2(acc[i][4], acc[i][5]);
        }
    }

    // fused logits: per-head partials over this thread's 6 cols.
    // A 6-col span [cg6, cg6+5] crosses at most one 16-col head boundary.
    int h_lo = cg6 >> 4;
    int h_hi = (cg6 + 5) >> 4;
    int b = (h_lo == h_hi) ? 6 : (16 - (cg6 & 15));   // cols in low head
#pragma unroll
    for (int i = 0; i < 4; i++) {
        float pel_lo = 0.f, per_lo = 0.f, pel_hi = 0.f, per_hi = 0.f;
#pragma unroll
        for (int c = 0; c < 6; c++) {
            float v = acc[i][c];
            float wa = als[cg6 + c], wb = ars[cg6 + c];
            if (c < b) { pel_lo = fmaf(v, wa, pel_lo); per_lo = fmaf(v, wb, per_lo); }
            else       { pel_hi = fmaf(v, wa, pel_hi); per_hi = fmaf(v, wb, per_hi); }
        }
        atomicAdd(&ELs[ng4 + i][h_lo], pel_lo);
        atomicAdd(&ERs[ng4 + i][h_lo], per_lo);
        if (h_hi != h_lo) {
            atomicAdd(&ELs[ng4 + i][h_hi], pel_hi);
            atomicAdd(&ERs[ng4 + i][h_hi], per_hi);
        }
    }
    __syncthreads();

    if (tid < GB_NODES) {
        int n = node_base + tid;
        if (n < N_NODES) {
            g_el[n] = make_float4(ELs[tid][0], ELs[tid][1], ELs[tid][2], 0.f);
            g_er[n] = make_float4(ERs[tid][0], ERs[tid][1], ERs[tid][2], 0.f);
        }
    }
}

// ---------------------------------------------------------------------------
// Kernel 2: in-degree histogram; atomic return value = edge rank in segment.
// ---------------------------------------------------------------------------
__global__ void k_hist(const int* __restrict__ dst) {
    int e = blockIdx.x * blockDim.x + threadIdx.x;
    if (e >= N_EDGES) return;
    int p = atomicAdd(&g_count[dst[e]], 1);
    g_pos[e] = (unsigned short)p;
}

// ---------------------------------------------------------------------------
// Kernel 3a/3b/3c: hierarchical exclusive scan of g_count -> g_off
// ---------------------------------------------------------------------------
__global__ __launch_bounds__(SCAN_B) void k_bsum() {
    __shared__ int sh[SCAN_B];
    int i = blockIdx.x * SCAN_B + threadIdx.x;
    sh[threadIdx.x] = (i < N_NODES) ? g_count[i] : 0;
    __syncthreads();
    for (int off = SCAN_B / 2; off > 0; off >>= 1) {
        if (threadIdx.x < off) sh[threadIdx.x] += sh[threadIdx.x + off];
        __syncthreads();
    }
    if (threadIdx.x == 0) g_bsum[blockIdx.x] = sh[0];
}

__global__ __launch_bounds__(512) void k_sscan() {
    __shared__ int sh[512];
    int t = threadIdx.x;
    sh[t] = (t < NB) ? g_bsum[t] : 0;
    __syncthreads();
    for (int off = 1; off < 512; off <<= 1) {
        int v = (t >= off) ? sh[t - off] : 0;
        __syncthreads();
        sh[t] += v;
        __syncthreads();
    }
    if (t < NB) g_bbase[t] = (t == 0) ? 0 : sh[t - 1];
}

__global__ __launch_bounds__(SCAN_B) void k_off() {
    __shared__ int sh[SCAN_B];
    int i = blockIdx.x * SCAN_B + threadIdx.x;
    int t = threadIdx.x;
    int c = (i < N_NODES) ? g_count[i] : 0;
    sh[t] = c;
    __syncthreads();
    for (int off = 1; off < SCAN_B; off <<= 1) {
        int v = (t >= off) ? sh[t - off] : 0;
        __syncthreads();
        sh[t] += v;
        __syncthreads();
    }
    if (i < N_NODES) {
        g_off[i] = g_bbase[blockIdx.x] + sh[t] - c;
    }
}

// ---------------------------------------------------------------------------
// Kernel 4: edge scatter — atomic-free, 4B payload. pos = off[d] + rank.
// ---------------------------------------------------------------------------
__global__ void k_scatter(const int* __restrict__ src, const int* __restrict__ dst) {
    int e = blockIdx.x * blockDim.x + threadIdx.x;
    if (e >= N_EDGES) return;
    int d = dst[e];
    int pos = g_off[d] + (int)g_pos[e];
    g_esrc[pos] = src[e];
}

// ---------------------------------------------------------------------------
// Kernel 5: per-dst aggregation, 12 threads/node, fp32 float4 gathers
// (R13 config — fp16 shadow retired after two controlled regressions).
// Attention recomputed: a = exp(leakyrelu(el[s].h + er[d].h)).
// Max-subtraction skipped: |e| <= ~4, softmax shift-invariant (fp32-safe).
// ---------------------------------------------------------------------------
__global__ __launch_bounds__(192) void k_agg(const float* __restrict__ lin,
                                             float* __restrict__ out) {
    int d = blockIdx.x * 16 + threadIdx.y;
    if (d >= N_NODES) return;
    int tx = threadIdx.x;       // 0..11
    int c4 = tx * 4;            // col base 0,4,...,44
    int h = tx >> 2;            // head 0..2

    int beg = g_off[d];
    int cnt = g_count[d];
    int end = beg + cnt;

    float4 R4 = g_er[d];
    float er_h = (h == 0) ? R4.x : ((h == 1) ? R4.y : R4.z);

    float4 num0 = make_float4(0.f, 0.f, 0.f, 0.f);
    float4 num1 = make_float4(0.f, 0.f, 0.f, 0.f);
    float den0 = 0.f, den1 = 0.f;

    int p = beg;
    for (; p + 2 <= end; p += 2) {
        int s0 = g_esrc[p];
        int s1 = g_esrc[p + 1];
        float4 L0 = g_el[s0];
        float4 L1 = g_el[s1];
        float4 f0 = *(const float4*)(g_feat + (size_t)s0 * HD + c4);
        float4 f1 = *(const float4*)(g_feat + (size_t)s1 * HD + c4);
        float v0 = ((h == 0) ? L0.x : ((h == 1) ? L0.y : L0.z)) + er_h;
        float v1 = ((h == 0) ? L1.x : ((h == 1) ? L1.y : L1.z)) + er_h;
        v0 = v0 > 0.f ? v0 : NEG_SLOPE * v0;
        v1 = v1 > 0.f ? v1 : NEG_SLOPE * v1;
        float a0 = __expf(v0);
        float a1 = __expf(v1);
        num0.x = fmaf(a0, f0.x, num0.x); num0.y = fmaf(a0, f0.y, num0.y);
        num0.z = fmaf(a0, f0.z, num0.z); num0.w = fmaf(a0, f0.w, num0.w);
        den0 += a0;
        num1.x = fmaf(a1, f1.x, num1.x); num1.y = fmaf(a1, f1.y, num1.y);
        num1.z = fmaf(a1, f1.z, num1.z); num1.w = fmaf(a1, f1.w, num1.w);
        den1 += a1;
    }
    if (p < end) {
        int s = g_esrc[p];
        float4 L = g_el[s];
        float4 f = *(const float4*)(g_feat + (size_t)s * HD + c4);
        float v = ((h == 0) ? L.x : ((h == 1) ? L.y : L.z)) + er_h;
        v = v > 0.f ? v : NEG_SLOPE * v;
        float a = __expf(v);
        num0.x = fmaf(a, f.x, num0.x); num0.y = fmaf(a, f.y, num0.y);
        num0.z = fmaf(a, f.z, num0.z); num0.w = fmaf(a, f.w, num0.w);
        den0 += a;
    }

    float den = den0 + den1;
    float inv = (cnt > 0) ? (1.f / den) : 0.f;
    float l = lin[d];
    float4 fd = *(const float4*)(g_feat + (size_t)d * HD + c4);
    float4 r;
    r.x = (1.f - l) * ((num0.x + num1.x) * inv) + l * fd.x;
    r.y = (1.f - l) * ((num0.y + num1.y) * inv) + l * fd.y;
    r.z = (1.f - l) * ((num0.z + num1.z) * inv) + l * fd.z;
    r.w = (1.f - l) * ((num0.w + num1.w) * inv) + l * fd.w;
    *(float4*)(out + (size_t)d * HD + c4) = r;
}

// ---------------------------------------------------------------------------
// Launch order puts k_gemm in profile slot 4 (ncu captures the 4th launch).
// ---------------------------------------------------------------------------
extern "C" void kernel_launch(void* const* d_in, const int* in_sizes, int n_in,
                              void* d_out, int out_size) {
    const float* x   = (const float*)d_in[0];
    const float* W   = (const float*)d_in[1];
    const float* al  = (const float*)d_in[2];
    const float* ar  = (const float*)d_in[3];
    const float* lin = (const float*)d_in[4];
    const int*   src = (const int*)d_in[5];
    const int*   dst = (const int*)d_in[6];
    float* out = (float*)d_out;

    k_init<<<(N_NODES + 255) / 256, 256>>>();
    k_hist<<<(N_EDGES + 255) / 256, 256>>>(dst);
    k_bsum<<<NB, SCAN_B>>>();
    k_gemm<<<(N_NODES + GB_NODES - 1) / GB_NODES, GB_THREADS>>>(x, W, al, ar); // slot 4
    k_sscan<<<1, 512>>>();
    k_off<<<NB, SCAN_B>>>();
    k_scatter<<<(N_EDGES + 255) / 256, 256>>>(src, dst);
    dim3 aggBlock(12, 16);
    k_agg<<<(N_NODES + 15) / 16, aggBlock>>>(lin, out);
}

// round 16
// speedup vs baseline: 1.0429x; 1.0160x over previous
#include <cuda_runtime.h>
#include <cuda_bf16.h>

#define N_NODES 100000
#define N_EDGES 1600000
#define F_IN 128
#define N_H 3
#define N_D 16
#define HD 48
#define NEG_SLOPE 0.2f

#define SCAN_B 256
#define NB ((N_NODES + SCAN_B - 1) / SCAN_B)   // 391

#define GB_NODES 128          // nodes per gemm block
#define GB_THREADS 256

// Scratch (device globals)
__device__ float  g_feat[N_NODES * HD];     // projected features (N,48)
__device__ float4 g_el[N_NODES];            // (el0,el1,el2,_)
__device__ float4 g_er[N_NODES];            // (er0,er1,er2,_)
__device__ int    g_esrc[N_EDGES];          // src index per edge, grouped by dst
__device__ unsigned short g_pos[N_EDGES];   // edge rank within its dst segment
__device__ int    g_count[N_NODES];         // in-degree
__device__ int    g_off[N_NODES];           // CSR segment start
__device__ int    g_bsum[NB];               // per-block count sums
__device__ int    g_bbase[NB];              // exclusive scan of block sums

// ---------------------------------------------------------------------------
// Kernel 0: zero degree counters
// ---------------------------------------------------------------------------
__global__ void k_init() {
    int i = blockIdx.x * blockDim.x + threadIdx.x;
    if (i < N_NODES) g_count[i] = 0;
}

// ---------------------------------------------------------------------------
// Kernel 1: register-tiled GEMM, DOUBLE-BUFFERED x staging + fused logits.
// Per chunk: STS -> ONE sync -> prefetch next LDG (overlaps compute) ->
// compute. Program order makes writing buf_i at iteration i+2 safe: every
// thread passed sync_{i+1} only after finishing compute_i.
// ---------------------------------------------------------------------------
__global__ __launch_bounds__(GB_THREADS) void k_gemm(const float* __restrict__ x,
                                                     const float* __restrict__ W,
                                                     const float* __restrict__ al,
                                                     const float* __restrict__ ar)
{
    __shared__ __align__(16) float Wt[F_IN][HD];         // Wt[k][j] = W[j*F_IN+k]
    __shared__ __align__(16) float Xs[2][16][GB_NODES];  // double-buffered x chunks
    __shared__ float ELs[GB_NODES][4];                   // per-head el partials
    __shared__ float ERs[GB_NODES][4];                   // per-head er partials
    __shared__ float als[HD], ars[HD];

    int tid = threadIdx.x;
    for (int i = tid; i < HD * F_IN; i += GB_THREADS) {
        int j = i / F_IN, k = i % F_IN;
        Wt[k][j] = W[i];
    }
    if (tid < HD) {
        als[tid] = al[tid];
        ars[tid] = ar[tid];
    }
    for (int i = tid; i < GB_NODES * 4; i += GB_THREADS) {
        ELs[i >> 2][i & 3] = 0.f;
        ERs[i >> 2][i & 3] = 0.f;
    }

    int node_base = blockIdx.x * GB_NODES;
    int ng = tid >> 3;            // node group 0..31 (4 nodes each)
    int cg = tid & 7;             // col group 0..7 (6 cols each)
    int ng4 = ng * 4;
    int cg6 = cg * 6;

    int ln = tid & 127;
    int lk = (tid >> 7) * 8;
    int gnode = node_base + ln;
    bool ldok = (gnode < N_NODES);
    const float* xrow = x + (size_t)gnode * F_IN + lk;

    float acc[4][6];
#pragma unroll
    for (int i = 0; i < 4; i++)
#pragma unroll
        for (int c = 0; c < 6; c++) acc[i][c] = 0.f;

    // preload chunk 0
    float4 v0 = ldok ? *(const float4*)(xrow + 0) : make_float4(0.f,0.f,0.f,0.f);
    float4 v1 = ldok ? *(const float4*)(xrow + 4) : make_float4(0.f,0.f,0.f,0.f);

#pragma unroll 2
    for (int c = 0; c < 8; c++) {
        int buf = c & 1;
        Xs[buf][lk + 0][ln] = v0.x; Xs[buf][lk + 1][ln] = v0.y;
        Xs[buf][lk + 2][ln] = v0.z; Xs[buf][lk + 3][ln] = v0.w;
        Xs[buf][lk + 4][ln] = v1.x; Xs[buf][lk + 5][ln] = v1.y;
        Xs[buf][lk + 6][ln] = v1.z; Xs[buf][lk + 7][ln] = v1.w;
        __syncthreads();

        if (c < 7) {    // prefetch next chunk while computing this one
            int kn = (c + 1) * 16;
            v0 = ldok ? *(const float4*)(xrow + kn)     : make_float4(0.f,0.f,0.f,0.f);
            v1 = ldok ? *(const float4*)(xrow + kn + 4) : make_float4(0.f,0.f,0.f,0.f);
        }

        int kk = c * 16;
#pragma unroll
        for (int k = 0; k < 16; k++) {
            float4 a = *(const float4*)&Xs[buf][k][ng4];       // LDS.128, bcast
            const float2* wr = (const float2*)&Wt[kk + k][cg6];
            float2 w01 = wr[0];
            float2 w23 = wr[1];
            float2 w45 = wr[2];
            acc[0][0] = fmaf(a.x, w01.x, acc[0][0]); acc[0][1] = fmaf(a.x, w01.y, acc[0][1]);
            acc[0][2] = fmaf(a.x, w23.x, acc[0][2]); acc[0][3] = fmaf(a.x, w23.y, acc[0][3]);
            acc[0][4] = fmaf(a.x, w45.x, acc[0][4]); acc[0][5] = fmaf(a.x, w45.y, acc[0][5]);
            acc[1][0] = fmaf(a.y, w01.x, acc[1][0]); acc[1][1] = fmaf(a.y, w01.y, acc[1][1]);
            acc[1][2] = fmaf(a.y, w23.x, acc[1][2]); acc[1][3] = fmaf(a.y, w23.y, acc[1][3]);
            acc[1][4] = fmaf(a.y, w45.x, acc[1][4]); acc[1][5] = fmaf(a.y, w45.y, acc[1][5]);
            acc[2][0] = fmaf(a.z, w01.x, acc[2][0]); acc[2][1] = fmaf(a.z, w01.y, acc[2][1]);
            acc[2][2] = fmaf(a.z, w23.x, acc[2][2]); acc[2][3] = fmaf(a.z, w23.y, acc[2][3]);
            acc[2][4] = fmaf(a.z, w45.x, acc[2][4]); acc[2][5] = fmaf(a.z, w45.y, acc[2][5]);
            acc[3][0] = fmaf(a.w, w01.x, acc[3][0]); acc[3][1] = fmaf(a.w, w01.y, acc[3][1]);
            acc[3][2] = fmaf(a.w, w23.x, acc[3][2]); acc[3][3] = fmaf(a.w, w23.y, acc[3][3]);
            acc[3][4] = fmaf(a.w, w45.x, acc[3][4]); acc[3][5] = fmaf(a.w, w45.y, acc[3][5]);
        }
    }

    // feat stores
#pragma unroll
    for (int i = 0; i < 4; i++) {
        int n = node_base + ng4 + i;
        if (n < N_NODES) {
            float* dstp = g_feat + (size_t)n * HD + cg6;
            *(float2*)(dstp + 0) = make_float2(acc[i][0], acc[i][1]);
            *(float2*)(dstp + 2) = make_float2(acc[i][2], acc[i][3]);
            *(float2*)(dstp + 4) = make_float2(acc[i][4], acc[i][5]);
        }
    }

    // fused logits: per-head partials over this thread's 6 cols.
    int h_lo = cg6 >> 4;
    int h_hi = (cg6 + 5) >> 4;
    int b = (h_lo == h_hi) ? 6 : (16 - (cg6 & 15));   // cols in low head
#pragma unroll
    for (int i = 0; i < 4; i++) {
        float pel_lo = 0.f, per_lo = 0.f, pel_hi = 0.f, per_hi = 0.f;
#pragma unroll
        for (int c = 0; c < 6; c++) {
            float v = acc[i][c];
            float wa = als[cg6 + c], wb = ars[cg6 + c];
            if (c < b) { pel_lo = fmaf(v, wa, pel_lo); per_lo = fmaf(v, wb, per_lo); }
            else       { pel_hi = fmaf(v, wa, pel_hi); per_hi = fmaf(v, wb, per_hi); }
        }
        atomicAdd(&ELs[ng4 + i][h_lo], pel_lo);
        atomicAdd(&ERs[ng4 + i][h_lo], per_lo);
        if (h_hi != h_lo) {
            atomicAdd(&ELs[ng4 + i][h_hi], pel_hi);
            atomicAdd(&ERs[ng4 + i][h_hi], per_hi);
        }
    }
    __syncthreads();

    if (tid < GB_NODES) {
        int n = node_base + tid;
        if (n < N_NODES) {
            g_el[n] = make_float4(ELs[tid][0], ELs[tid][1], ELs[tid][2], 0.f);
            g_er[n] = make_float4(ERs[tid][0], ERs[tid][1], ERs[tid][2], 0.f);
        }
    }
}

// ---------------------------------------------------------------------------
// Kernel 2: in-degree histogram; atomic return value = edge rank in segment.
// ---------------------------------------------------------------------------
__global__ void k_hist(const int* __restrict__ dst) {
    int e = blockIdx.x * blockDim.x + threadIdx.x;
    if (e >= N_EDGES) return;
    int p = atomicAdd(&g_count[dst[e]], 1);
    g_pos[e] = (unsigned short)p;
}

// ---------------------------------------------------------------------------
// Kernel 3a/3b/3c: hierarchical exclusive scan of g_count -> g_off
// ---------------------------------------------------------------------------
__global__ __launch_bounds__(SCAN_B) void k_bsum() {
    __shared__ int sh[SCAN_B];
    int i = blockIdx.x * SCAN_B + threadIdx.x;
    sh[threadIdx.x] = (i < N_NODES) ? g_count[i] : 0;
    __syncthreads();
    for (int off = SCAN_B / 2; off > 0; off >>= 1) {
        if (threadIdx.x < off) sh[threadIdx.x] += sh[threadIdx.x + off];
        __syncthreads();
    }
    if (threadIdx.x == 0) g_bsum[blockIdx.x] = sh[0];
}

__global__ __launch_bounds__(512) void k_sscan() {
    __shared__ int sh[512];
    int t = threadIdx.x;
    sh[t] = (t < NB) ? g_bsum[t] : 0;
    __syncthreads();
    for (int off = 1; off < 512; off <<= 1) {
        int v = (t >= off) ? sh[t - off] : 0;
        __syncthreads();
        sh[t] += v;
        __syncthreads();
    }
    if (t < NB) g_bbase[t] = (t == 0) ? 0 : sh[t - 1];
}

__global__ __launch_bounds__(SCAN_B) void k_off() {
    __shared__ int sh[SCAN_B];
    int i = blockIdx.x * SCAN_B + threadIdx.x;
    int t = threadIdx.x;
    int c = (i < N_NODES) ? g_count[i] : 0;
    sh[t] = c;
    __syncthreads();
    for (int off = 1; off < SCAN_B; off <<= 1) {
        int v = (t >= off) ? sh[t - off] : 0;
        __syncthreads();
        sh[t] += v;
        __syncthreads();
    }
    if (i < N_NODES) {
        g_off[i] = g_bbase[blockIdx.x] + sh[t] - c;
    }
}

// ---------------------------------------------------------------------------
// Kernel 4: edge scatter — atomic-free, 4B payload. pos = off[d] + rank.
// ---------------------------------------------------------------------------
__global__ void k_scatter(const int* __restrict__ src, const int* __restrict__ dst) {
    int e = blockIdx.x * blockDim.x + threadIdx.x;
    if (e >= N_EDGES) return;
    int d = dst[e];
    int pos = g_off[d] + (int)g_pos[e];
    g_esrc[pos] = src[e];
}

// ---------------------------------------------------------------------------
// Kernel 5: per-dst aggregation, 12 threads/node, fp32 float4 gathers.
// Attention recomputed: a = exp(leakyrelu(el[s].h + er[d].h)).
// Max-subtraction skipped: |e| <= ~4, softmax shift-invariant (fp32-safe).
// ---------------------------------------------------------------------------
__global__ __launch_bounds__(192) void k_agg(const float* __restrict__ lin,
                                             float* __restrict__ out) {
    int d = blockIdx.x * 16 + threadIdx.y;
    if (d >= N_NODES) return;
    int tx = threadIdx.x;       // 0..11
    int c4 = tx * 4;            // col base 0,4,...,44
    int h = tx >> 2;            // head 0..2

    int beg = g_off[d];
    int cnt = g_count[d];
    int end = beg + cnt;

    float4 R4 = g_er[d];
    float er_h = (h == 0) ? R4.x : ((h == 1) ? R4.y : R4.z);

    float4 num0 = make_float4(0.f, 0.f, 0.f, 0.f);
    float4 num1 = make_float4(0.f, 0.f, 0.f, 0.f);
    float den0 = 0.f, den1 = 0.f;

    int p = beg;
    for (; p + 2 <= end; p += 2) {
        int s0 = g_esrc[p];
        int s1 = g_esrc[p + 1];
        float4 L0 = g_el[s0];
        float4 L1 = g_el[s1];
        float4 f0 = *(const float4*)(g_feat + (size_t)s0 * HD + c4);
        float4 f1 = *(const float4*)(g_feat + (size_t)s1 * HD + c4);
        float v0 = ((h == 0) ? L0.x : ((h == 1) ? L0.y : L0.z)) + er_h;
        float v1 = ((h == 0) ? L1.x : ((h == 1) ? L1.y : L1.z)) + er_h;
        v0 = v0 > 0.f ? v0 : NEG_SLOPE * v0;
        v1 = v1 > 0.f ? v1 : NEG_SLOPE * v1;
        float a0 = __expf(v0);
        float a1 = __expf(v1);
        num0.x = fmaf(a0, f0.x, num0.x); num0.y = fmaf(a0, f0.y, num0.y);
        num0.z = fmaf(a0, f0.z, num0.z); num0.w = fmaf(a0, f0.w, num0.w);
        den0 += a0;
        num1.x = fmaf(a1, f1.x, num1.x); num1.y = fmaf(a1, f1.y, num1.y);
        num1.z = fmaf(a1, f1.z, num1.z); num1.w = fmaf(a1, f1.w, num1.w);
        den1 += a1;
    }
    if (p < end) {
        int s = g_esrc[p];
        float4 L = g_el[s];
        float4 f = *(const float4*)(g_feat + (size_t)s * HD + c4);
        float v = ((h == 0) ? L.x : ((h == 1) ? L.y : L.z)) + er_h;
        v = v > 0.f ? v : NEG_SLOPE * v;
        float a = __expf(v);
        num0.x = fmaf(a, f.x, num0.x); num0.y = fmaf(a, f.y, num0.y);
        num0.z = fmaf(a, f.z, num0.z); num0.w = fmaf(a, f.w, num0.w);
        den0 += a;
    }

    float den = den0 + den1;
    float inv = (cnt > 0) ? (1.f / den) : 0.f;
    float l = lin[d];
    float4 fd = *(const float4*)(g_feat + (size_t)d * HD + c4);
    float4 r;
    r.x = (1.f - l) * ((num0.x + num1.x) * inv) + l * fd.x;
    r.y = (1.f - l) * ((num0.y + num1.y) * inv) + l * fd.y;
    r.z = (1.f - l) * ((num0.z + num1.z) * inv) + l * fd.z;
    r.w = (1.f - l) * ((num0.w + num1.w) * inv) + l * fd.w;
    *(float4*)(out + (size_t)d * HD + c4) = r;
}

// ---------------------------------------------------------------------------
// Launch order puts k_gemm in profile slot 4 (ncu captures the 4th launch).
// ---------------------------------------------------------------------------
extern "C" void kernel_launch(void* const* d_in, const int* in_sizes, int n_in,
                              void* d_out, int out_size) {
    const float* x   = (const float*)d_in[0];
    const float* W   = (const float*)d_in[1];
    const float* al  = (const float*)d_in[2];
    const float* ar  = (const float*)d_in[3];
    const float* lin = (const float*)d_in[4];
    const int*   src = (const int*)d_in[5];
    const int*   dst = (const int*)d_in[6];
    float* out = (float*)d_out;

    k_init<<<(N_NODES + 255) / 256, 256>>>();
    k_hist<<<(N_EDGES + 255) / 256, 256>>>(dst);
    k_bsum<<<NB, SCAN_B>>>();
    k_gemm<<<(N_NODES + GB_NODES - 1) / GB_NODES, GB_THREADS>>>(x, W, al, ar); // slot 4
    k_sscan<<<1, 512>>>();
    k_off<<<NB, SCAN_B>>>();
    k_scatter<<<(N_EDGES + 255) / 256, 256>>>(src, dst);
    dim3 aggBlock(12, 16);
    k_agg<<<(N_NODES + 15) / 16, aggBlock>>>(lin, out);
}

// round 17
// speedup vs baseline: 1.0582x; 1.0147x over previous
#include <cuda_runtime.h>
#include <cuda_bf16.h>

#define N_NODES 100000
#define N_EDGES 1600000
#define F_IN 128
#define N_H 3
#define N_D 16
#define HD 48
#define NEG_SLOPE 0.2f

#define SCAN_B 256
#define NB ((N_NODES + SCAN_B - 1) / SCAN_B)   // 391

#define GB_NODES 256          // nodes per gemm block
#define GB_THREADS 256
#define KC 8                  // k-chunk size

// Scratch (device globals)
__device__ float  g_feat[N_NODES * HD];     // projected features (N,48)
__device__ float4 g_el[N_NODES];            // (el0,el1,el2,_)
__device__ float4 g_er[N_NODES];            // (er0,er1,er2,_)
__device__ int    g_esrc[N_EDGES];          // src index per edge, grouped by dst
__device__ unsigned short g_pos[N_EDGES];   // edge rank within its dst segment
__device__ int    g_count[N_NODES];         // in-degree
__device__ int    g_off[N_NODES];           // CSR segment start
__device__ int    g_bsum[NB];               // per-block count sums
__device__ int    g_bbase[NB];              // exclusive scan of block sums

// ---------------------------------------------------------------------------
// Kernel 0: zero degree counters
// ---------------------------------------------------------------------------
__global__ void k_init() {
    int i = blockIdx.x * blockDim.x + threadIdx.x;
    if (i < N_NODES) g_count[i] = 0;
}

// ---------------------------------------------------------------------------
// Kernel 1: register-tiled GEMM, 4 nodes x 12 cols per thread (48 accums).
// Per k-step: 4 LDS.128 feed 48 FFMA (was 4 LDS per 24 FFMA -> LDS-bound).
// Double-buffered Xs (k-chunks of 8), fused logits epilogue.
// ---------------------------------------------------------------------------
__global__ __launch_bounds__(GB_THREADS) void k_gemm(const float* __restrict__ x,
                                                     const float* __restrict__ W,
                                                     const float* __restrict__ al,
                                                     const float* __restrict__ ar)
{
    __shared__ __align__(16) float Wt[F_IN][HD];         // 24KB, Wt[k][j]=W[j*F_IN+k]
    __shared__ __align__(16) float Xs[2][KC][GB_NODES];  // 16KB double-buffered
    __shared__ float ELs[GB_NODES][3];                   // 3KB
    __shared__ float ERs[GB_NODES][3];                   // 3KB
    __shared__ float als[HD], ars[HD];

    int tid = threadIdx.x;
    for (int i = tid; i < HD * F_IN; i += GB_THREADS) {
        int j = i / F_IN, k = i % F_IN;
        Wt[k][j] = W[i];
    }
    if (tid < HD) {
        als[tid] = al[tid];
        ars[tid] = ar[tid];
    }
    for (int i = tid; i < GB_NODES * 3; i += GB_THREADS) {
        ELs[i / 3][i % 3] = 0.f;
        ERs[i / 3][i % 3] = 0.f;
    }

    int node_base = blockIdx.x * GB_NODES;
    int ng = tid >> 2;            // node group 0..63 (4 nodes each)
    int cg = tid & 3;             // col group 0..3 (12 cols each)
    int ng4 = ng * 4;
    int cg12 = cg * 12;

    // x loader: thread tid loads node tid, k-chunk [kk, kk+7] (2 float4s)
    int gnode = node_base + tid;
    bool ldok = (gnode < N_NODES);
    const float* xrow = x + (size_t)gnode * F_IN;

    float acc[4][12];
#pragma unroll
    for (int i = 0; i < 4; i++)
#pragma unroll
        for (int c = 0; c < 12; c++) acc[i][c] = 0.f;

    // preload chunk 0
    float4 v0 = ldok ? *(const float4*)(xrow + 0) : make_float4(0.f,0.f,0.f,0.f);
    float4 v1 = ldok ? *(const float4*)(xrow + 4) : make_float4(0.f,0.f,0.f,0.f);

    for (int c = 0; c < F_IN / KC; c++) {     // 16 chunks
        int buf = c & 1;
        Xs[buf][0][tid] = v0.x; Xs[buf][1][tid] = v0.y;
        Xs[buf][2][tid] = v0.z; Xs[buf][3][tid] = v0.w;
        Xs[buf][4][tid] = v1.x; Xs[buf][5][tid] = v1.y;
        Xs[buf][6][tid] = v1.z; Xs[buf][7][tid] = v1.w;
        __syncthreads();

        if (c < F_IN / KC - 1) {  // prefetch next chunk during compute
            int kn = (c + 1) * KC;
            v0 = ldok ? *(const float4*)(xrow + kn)     : make_float4(0.f,0.f,0.f,0.f);
            v1 = ldok ? *(const float4*)(xrow + kn + 4) : make_float4(0.f,0.f,0.f,0.f);
        }

        int kk = c * KC;
#pragma unroll
        for (int k = 0; k < KC; k++) {
            float4 a = *(const float4*)&Xs[buf][k][ng4];          // LDS.128
            const float4* wr = (const float4*)&Wt[kk + k][cg12];  // 3x LDS.128
            float4 wA = wr[0];
            float4 wB = wr[1];
            float4 wC = wr[2];
#pragma unroll
            for (int i = 0; i < 4; i++) {
                float ai = (i == 0) ? a.x : (i == 1) ? a.y : (i == 2) ? a.z : a.w;
                acc[i][0]  = fmaf(ai, wA.x, acc[i][0]);
                acc[i][1]  = fmaf(ai, wA.y, acc[i][1]);
                acc[i][2]  = fmaf(ai, wA.z, acc[i][2]);
                acc[i][3]  = fmaf(ai, wA.w, acc[i][3]);
                acc[i][4]  = fmaf(ai, wB.x, acc[i][4]);
                acc[i][5]  = fmaf(ai, wB.y, acc[i][5]);
                acc[i][6]  = fmaf(ai, wB.z, acc[i][6]);
                acc[i][7]  = fmaf(ai, wB.w, acc[i][7]);
                acc[i][8]  = fmaf(ai, wC.x, acc[i][8]);
                acc[i][9]  = fmaf(ai, wC.y, acc[i][9]);
                acc[i][10] = fmaf(ai, wC.z, acc[i][10]);
                acc[i][11] = fmaf(ai, wC.w, acc[i][11]);
            }
        }
    }

    // feat stores: 4 nodes x 12 cols = 3 float4 per node (48B offset: aligned)
#pragma unroll
    for (int i = 0; i < 4; i++) {
        int n = node_base + ng4 + i;
        if (n < N_NODES) {
            float4* dstp = (float4*)(g_feat + (size_t)n * HD + cg12);
            dstp[0] = make_float4(acc[i][0], acc[i][1], acc[i][2],  acc[i][3]);
            dstp[1] = make_float4(acc[i][4], acc[i][5], acc[i][6],  acc[i][7]);
            dstp[2] = make_float4(acc[i][8], acc[i][9], acc[i][10], acc[i][11]);
        }
    }

    // fused logits: a 12-col span crosses at most one 16-col head boundary.
    int h_lo = cg12 >> 4;
    int h_hi = (cg12 + 11) >> 4;
    int b = (h_lo == h_hi) ? 12 : (16 - (cg12 & 15));   // cols in low head
#pragma unroll
    for (int i = 0; i < 4; i++) {
        float pel_lo = 0.f, per_lo = 0.f, pel_hi = 0.f, per_hi = 0.f;
#pragma unroll
        for (int c = 0; c < 12; c++) {
            float v = acc[i][c];
            float wa = als[cg12 + c], wb = ars[cg12 + c];
            if (c < b) { pel_lo = fmaf(v, wa, pel_lo); per_lo = fmaf(v, wb, per_lo); }
            else       { pel_hi = fmaf(v, wa, pel_hi); per_hi = fmaf(v, wb, per_hi); }
        }
        atomicAdd(&ELs[ng4 + i][h_lo], pel_lo);
        atomicAdd(&ERs[ng4 + i][h_lo], per_lo);
        if (h_hi != h_lo) {
            atomicAdd(&ELs[ng4 + i][h_hi], pel_hi);
            atomicAdd(&ERs[ng4 + i][h_hi], per_hi);
        }
    }
    __syncthreads();

    {
        int n = node_base + tid;
        if (n < N_NODES) {
            g_el[n] = make_float4(ELs[tid][0], ELs[tid][1], ELs[tid][2], 0.f);
            g_er[n] = make_float4(ERs[tid][0], ERs[tid][1], ERs[tid][2], 0.f);
        }
    }
}

// ---------------------------------------------------------------------------
// Kernel 2: in-degree histogram; atomic return value = edge rank in segment.
// ---------------------------------------------------------------------------
__global__ void k_hist(const int* __restrict__ dst) {
    int e = blockIdx.x * blockDim.x + threadIdx.x;
    if (e >= N_EDGES) return;
    int p = atomicAdd(&g_count[dst[e]], 1);
    g_pos[e] = (unsigned short)p;
}

// ---------------------------------------------------------------------------
// Kernel 3a/3b/3c: hierarchical exclusive scan of g_count -> g_off
// ---------------------------------------------------------------------------
__global__ __launch_bounds__(SCAN_B) void k_bsum() {
    __shared__ int sh[SCAN_B];
    int i = blockIdx.x * SCAN_B + threadIdx.x;
    sh[threadIdx.x] = (i < N_NODES) ? g_count[i] : 0;
    __syncthreads();
    for (int off = SCAN_B / 2; off > 0; off >>= 1) {
        if (threadIdx.x < off) sh[threadIdx.x] += sh[threadIdx.x + off];
        __syncthreads();
    }
    if (threadIdx.x == 0) g_bsum[blockIdx.x] = sh[0];
}

__global__ __launch_bounds__(512) void k_sscan() {
    __shared__ int sh[512];
    int t = threadIdx.x;
    sh[t] = (t < NB) ? g_bsum[t] : 0;
    __syncthreads();
    for (int off = 1; off < 512; off <<= 1) {
        int v = (t >= off) ? sh[t - off] : 0;
        __syncthreads();
        sh[t] += v;
        __syncthreads();
    }
    if (t < NB) g_bbase[t] = (t == 0) ? 0 : sh[t - 1];
}

__global__ __launch_bounds__(SCAN_B) void k_off() {
    __shared__ int sh[SCAN_B];
    int i = blockIdx.x * SCAN_B + threadIdx.x;
    int t = threadIdx.x;
    int c = (i < N_NODES) ? g_count[i] : 0;
    sh[t] = c;
    __syncthreads();
    for (int off = 1; off < SCAN_B; off <<= 1) {
        int v = (t >= off) ? sh[t - off] : 0;
        __syncthreads();
        sh[t] += v;
        __syncthreads();
    }
    if (i < N_NODES) {
        g_off[i] = g_bbase[blockIdx.x] + sh[t] - c;
    }
}

// ---------------------------------------------------------------------------
// Kernel 4: edge scatter — atomic-free, 4B payload. pos = off[d] + rank.
// ---------------------------------------------------------------------------
__global__ void k_scatter(const int* __restrict__ src, const int* __restrict__ dst) {
    int e = blockIdx.x * blockDim.x + threadIdx.x;
    if (e >= N_EDGES) return;
    int d = dst[e];
    int pos = g_off[d] + (int)g_pos[e];
    g_esrc[pos] = src[e];
}

// ---------------------------------------------------------------------------
// Kernel 5: per-dst aggregation, 12 threads/node, fp32 float4 gathers.
// Attention recomputed: a = exp(leakyrelu(el[s].h + er[d].h)).
// Max-subtraction skipped: |e| <= ~4, softmax shift-invariant (fp32-safe).
// ---------------------------------------------------------------------------
__global__ __launch_bounds__(192) void k_agg(const float* __restrict__ lin,
                                             float* __restrict__ out) {
    int d = blockIdx.x * 16 + threadIdx.y;
    if (d >= N_NODES) return;
    int tx = threadIdx.x;       // 0..11
    int c4 = tx * 4;            // col base 0,4,...,44
    int h = tx >> 2;            // head 0..2

    int beg = g_off[d];
    int cnt = g_count[d];
    int end = beg + cnt;

    float4 R4 = g_er[d];
    float er_h = (h == 0) ? R4.x : ((h == 1) ? R4.y : R4.z);

    float4 num0 = make_float4(0.f, 0.f, 0.f, 0.f);
    float4 num1 = make_float4(0.f, 0.f, 0.f, 0.f);
    float den0 = 0.f, den1 = 0.f;

    int p = beg;
    for (; p + 2 <= end; p += 2) {
        int s0 = g_esrc[p];
        int s1 = g_esrc[p + 1];
        float4 L0 = g_el[s0];
        float4 L1 = g_el[s1];
        float4 f0 = *(const float4*)(g_feat + (size_t)s0 * HD + c4);
        float4 f1 = *(const float4*)(g_feat + (size_t)s1 * HD + c4);
        float v0 = ((h == 0) ? L0.x : ((h == 1) ? L0.y : L0.z)) + er_h;
        float v1 = ((h == 0) ? L1.x : ((h == 1) ? L1.y : L1.z)) + er_h;
        v0 = v0 > 0.f ? v0 : NEG_SLOPE * v0;
        v1 = v1 > 0.f ? v1 : NEG_SLOPE * v1;
        float a0 = __expf(v0);
        float a1 = __expf(v1);
        num0.x = fmaf(a0, f0.x, num0.x); num0.y = fmaf(a0, f0.y, num0.y);
        num0.z = fmaf(a0, f0.z, num0.z); num0.w = fmaf(a0, f0.w, num0.w);
        den0 += a0;
        num1.x = fmaf(a1, f1.x, num1.x); num1.y = fmaf(a1, f1.y, num1.y);
        num1.z = fmaf(a1, f1.z, num1.z); num1.w = fmaf(a1, f1.w, num1.w);
        den1 += a1;
    }
    if (p < end) {
        int s = g_esrc[p];
        float4 L = g_el[s];
        float4 f = *(const float4*)(g_feat + (size_t)s * HD + c4);
        float v = ((h == 0) ? L.x : ((h == 1) ? L.y : L.z)) + er_h;
        v = v > 0.f ? v : NEG_SLOPE * v;
        float a = __expf(v);
        num0.x = fmaf(a, f.x, num0.x); num0.y = fmaf(a, f.y, num0.y);
        num0.z = fmaf(a, f.z, num0.z); num0.w = fmaf(a, f.w, num0.w);
        den0 += a;
    }

    float den = den0 + den1;
    float inv = (cnt > 0) ? (1.f / den) : 0.f;
    float l = lin[d];
    float4 fd = *(const float4*)(g_feat + (size_t)d * HD + c4);
    float4 r;
    r.x = (1.f - l) * ((num0.x + num1.x) * inv) + l * fd.x;
    r.y = (1.f - l) * ((num0.y + num1.y) * inv) + l * fd.y;
    r.z = (1.f - l) * ((num0.z + num1.z) * inv) + l * fd.z;
    r.w = (1.f - l) * ((num0.w + num1.w) * inv) + l * fd.w;
    *(float4*)(out + (size_t)d * HD + c4) = r;
}

// ---------------------------------------------------------------------------
// Launch order puts k_gemm in profile slot 4 (ncu captures the 4th launch).
// ---------------------------------------------------------------------------
extern "C" void kernel_launch(void* const* d_in, const int* in_sizes, int n_in,
                              void* d_out, int out_size) {
    const float* x   = (const float*)d_in[0];
    const float* W   = (const float*)d_in[1];
    const float* al  = (const float*)d_in[2];
    const float* ar  = (const float*)d_in[3];
    const float* lin = (const float*)d_in[4];
    const int*   src = (const int*)d_in[5];
    const int*   dst = (const int*)d_in[6];
    float* out = (float*)d_out;

    k_init<<<(N_NODES + 255) / 256, 256>>>();
    k_hist<<<(N_EDGES + 255) / 256, 256>>>(dst);
    k_bsum<<<NB, SCAN_B>>>();
    k_gemm<<<(N_NODES + GB_NODES - 1) / GB_NODES, GB_THREADS>>>(x, W, al, ar); // slot 4
    k_sscan<<<1, 512>>>();
    k_off<<<NB, SCAN_B>>>();
    k_scatter<<<(N_EDGES + 255) / 256, 256>>>(src, dst);
    dim3 aggBlock(12, 16);
    k_agg<<<(N_NODES + 15) / 16, aggBlock>>>(lin, out);
}